// round 1
// baseline (speedup 1.0000x reference)
#include <cuda_runtime.h>
#include <cstdint>

// ---------------- problem constants ----------------
#define TD          6
#define T_TREES     64
#define N_NODES     63
#define L_LEAVES    64
#define C_CLASSES   100
#define C_PAD       112          // padded class dim (8 groups x 14)
#define B_TOTAL     8192
#define D_DIM       512

// ---------------- tiling ----------------
#define TILE_B      128
#define KC          64
#define NCHUNK      (D_DIM / KC)            // 8
#define NSLICES     4
#define TREES_PER_SLICE (T_TREES / NSLICES) // 16
#define THREADS     256

// ---------------- shared layout (floats) ----------------
// bufA union:  [Xs (64x128) | Ws (64x65)]  OR  [lp (128x65)]
#define XS_SIZE     (KC * 128)              // 8192
#define WS_OFF      XS_SIZE
#define WS_SIZE     (64 * 65)               // 4160
#define LP_PITCH    65
#define DEC_OFF     (XS_SIZE + WS_SIZE)     // 12352  (>= 128*65 lp)
#define DEC_PITCH   65
#define MS_OFF      (DEC_OFF + 128 * DEC_PITCH) // 20672
#define SMEM_FLOATS (MS_OFF + L_LEAVES * C_PAD) // 27840
#define SMEM_BYTES  (SMEM_FLOATS * 4)           // 111360

// ---------------- device scratch (no allocation allowed) ----------------
__device__ float g_M[T_TREES * L_LEAVES * C_PAD];            // softmax(leaf_logits)*tw, zero padded
__device__ float g_part[NSLICES * B_TOTAL * C_CLASSES];      // per-slice partial outputs

// ---------------- f32x2 helpers (Blackwell packed fp32) ----------------
__device__ __forceinline__ unsigned long long pack2(float lo, float hi) {
    unsigned long long r;
    asm("mov.b64 %0, {%1, %2};" : "=l"(r) : "f"(lo), "f"(hi));
    return r;
}
__device__ __forceinline__ void unpack2(unsigned long long v, float& lo, float& hi) {
    asm("mov.b64 {%0, %1}, %2;" : "=f"(lo), "=f"(hi) : "l"(v));
}
__device__ __forceinline__ unsigned long long fma2(unsigned long long a,
                                                   unsigned long long b,
                                                   unsigned long long c) {
    unsigned long long d;
    asm("fma.rn.f32x2 %0, %1, %2, %3;" : "=l"(d) : "l"(a), "l"(b), "l"(c));
    return d;
}

// ================= kernel 1: M[t,l,c] = softmax(leaf_logits[t,l,:])[c] * tw[t] =================
// one warp per (t,l) row
__global__ void softmax_mat_kernel(const float* __restrict__ ll, const float* __restrict__ tw) {
    const int row  = blockIdx.x;          // t*64 + l
    const int lane = threadIdx.x;
    const float* src = ll + (size_t)row * C_CLASSES;

    float v[4];
#pragma unroll
    for (int q = 0; q < 4; ++q) {
        int c = lane + 32 * q;
        v[q] = (c < C_CLASSES) ? src[c] : -1e30f;
    }
    float mx = fmaxf(fmaxf(v[0], v[1]), fmaxf(v[2], v[3]));
#pragma unroll
    for (int o = 16; o; o >>= 1) mx = fmaxf(mx, __shfl_xor_sync(0xffffffffu, mx, o));

    float e[4];
    float s = 0.f;
#pragma unroll
    for (int q = 0; q < 4; ++q) {
        int c = lane + 32 * q;
        e[q] = (c < C_CLASSES) ? __expf(v[q] - mx) : 0.f;
        s += e[q];
    }
#pragma unroll
    for (int o = 16; o; o >>= 1) s += __shfl_xor_sync(0xffffffffu, s, o);

    const float scale = tw[row >> 6] / s;
    float* dst = g_M + (size_t)row * C_PAD;
#pragma unroll
    for (int q = 0; q < 4; ++q) {
        int c = lane + 32 * q;
        if (c < C_PAD) dst[c] = (c < C_CLASSES) ? e[q] * scale : 0.f;
    }
}

// ================= kernel 2: fused trees =================
// grid: (B/128, 4 slices).  256 threads, occupancy 2 -> 256 blocks resident in one wave.
__global__ void __launch_bounds__(THREADS, 2)
fused_tree_kernel(const float* __restrict__ x,
                  const float* __restrict__ W,
                  const float* __restrict__ bias) {
    extern __shared__ float sm[];
    float* Xs  = sm;                 // [k][col] col = b ^ (k&28), pitch 128
    float* Ws  = sm + WS_OFF;        // [n][k]   pitch 65 (row 63 zeroed)
    float* lp  = sm;                 // [b][l]   pitch 65 (union with Xs/Ws)
    float* dec = sm + DEC_OFF;       // [b][n]   pitch 65
    float* Ms  = sm + MS_OFF;        // [l][c]   pitch 112

    const int tid = threadIdx.x;
    const int ng  = tid & 7;         // n-group (GEMM1) == c-group (GEMM2)
    const int bq  = tid >> 3;        // 0..31
    const int bb  = bq << 2;         // base b within tile (4 rows per thread)
    const int b0  = blockIdx.x * TILE_B;
    const int sl  = blockIdx.y;

    unsigned long long accO[4][7];   // output acc: 4 b-rows x 7 c-pairs (14 classes)
#pragma unroll
    for (int i = 0; i < 4; ++i)
#pragma unroll
        for (int u = 0; u < 7; ++u) accO[i][u] = 0ULL;

    for (int tt = 0; tt < TREES_PER_SLICE; ++tt) {
        const int t = sl * TREES_PER_SLICE + tt;

        __syncthreads();  // previous tree's GEMM2 (reads lp, Ms) fully done

        // ---- stage Ms for this tree: 64*112 floats = 1792 float4 ----
        {
            const float4* src = (const float4*)(g_M + (size_t)t * (L_LEAVES * C_PAD));
            float4* dst = (float4*)Ms;
#pragma unroll
            for (int it = 0; it < 7; ++it) dst[it * 256 + tid] = src[it * 256 + tid];
        }

        // ---- GEMM1: logits[128 x 64] = Xtile @ Wt^T ----
        unsigned long long acc0[8], acc1[8];  // (bb,bb+1) and (bb+2,bb+3) pairs x 8 nodes
#pragma unroll
        for (int j = 0; j < 8; ++j) { acc0[j] = 0ULL; acc1[j] = 0ULL; }

        for (int ch = 0; ch < NCHUNK; ++ch) {
            const int k0 = ch * KC;
            __syncthreads();  // previous chunk consumed before restaging

            // stage Xs: 128 rows x 64 k = 2048 float4, swizzled k-major
#pragma unroll
            for (int it = 0; it < 8; ++it) {
                int e4 = it * 256 + tid;
                int k4 = e4 & 15, b = e4 >> 4;
                float4 v = *(const float4*)(x + (size_t)(b0 + b) * D_DIM + k0 + (k4 << 2));
                int kk  = k4 << 2;
                int col = b ^ ((k4 & 7) << 2);   // == b ^ (k & 28)
                Xs[(kk + 0) * 128 + col] = v.x;
                Xs[(kk + 1) * 128 + col] = v.y;
                Xs[(kk + 2) * 128 + col] = v.z;
                Xs[(kk + 3) * 128 + col] = v.w;
            }
            // stage Ws: 64 n x 64 k = 1024 float4, n-major pitch 65 (row 63 zero)
#pragma unroll
            for (int it = 0; it < 4; ++it) {
                int e4 = it * 256 + tid;
                int k4 = e4 & 15, n = e4 >> 4;
                float4 v = make_float4(0.f, 0.f, 0.f, 0.f);
                if (n < N_NODES)
                    v = *(const float4*)(W + ((size_t)t * N_NODES + n) * D_DIM + k0 + (k4 << 2));
                float* wp = Ws + n * 65 + (k4 << 2);
                wp[0] = v.x; wp[1] = v.y; wp[2] = v.z; wp[3] = v.w;
            }
            __syncthreads();

            // inner product: per k, 2 LDS.64 (x pairs) + 8 LDS.32 (w) + 16 FFMA2
#pragma unroll 4
            for (int k = 0; k < KC; ++k) {
                const int colb = bb ^ (k & 28);
                const float* xk = Xs + k * 128;
                unsigned long long x20 = *(const unsigned long long*)(xk + colb);
                unsigned long long x21 = *(const unsigned long long*)(xk + (colb ^ 2));
                const float* wk = Ws + k;
#pragma unroll
                for (int j = 0; j < 8; ++j) {
                    float w = wk[(ng + (j << 3)) * 65];
                    unsigned long long w2 = pack2(w, w);
                    acc0[j] = fma2(x20, w2, acc0[j]);
                    acc1[j] = fma2(x21, w2, acc1[j]);
                }
            }
        }

        // ---- bias + sigmoid -> dec ----
        {
            const float* bt = bias + t * N_NODES;
#pragma unroll
            for (int j = 0; j < 8; ++j) {
                int n = ng + (j << 3);
                float bz = (n < N_NODES) ? bt[n] : 0.f;
                float a, b2, c, d;
                unpack2(acc0[j], a, b2);
                unpack2(acc1[j], c, d);
                dec[(bb + 0) * DEC_PITCH + n] = 1.f / (1.f + __expf(-(a  + bz)));
                dec[(bb + 1) * DEC_PITCH + n] = 1.f / (1.f + __expf(-(b2 + bz)));
                dec[(bb + 2) * DEC_PITCH + n] = 1.f / (1.f + __expf(-(c  + bz)));
                dec[(bb + 3) * DEC_PITCH + n] = 1.f / (1.f + __expf(-(d  + bz)));
            }
        }
        __syncthreads();

        // ---- leaf probabilities: lp[b][l] = prod over depth ----
        {
            int b  = tid >> 1;
            int l0 = (tid & 1) << 5;
            const float* db = dec + b * DEC_PITCH;
            float* lpb = lp + b * LP_PITCH;
#pragma unroll
            for (int li = 0; li < 32; ++li) {
                int l = l0 + li;
                float p = 1.f;
#pragma unroll
                for (int d = 0; d < TD; ++d) {
                    int node = (1 << d) - 1 + (l >> (TD - d));
                    float v = db[node];
                    p *= ((l >> (TD - 1 - d)) & 1) ? v : (1.f - v);
                }
                lpb[l] = p;
            }
        }
        __syncthreads();

        // ---- GEMM2: accO += lp[128 x 64] @ Ms[64 x 112] ----
        {
            const int cbase = ng * 14;
#pragma unroll 4
            for (int l = 0; l < L_LEAVES; ++l) {
                unsigned long long xw[4];
#pragma unroll
                for (int i = 0; i < 4; ++i) {
                    float v = lp[(bb + i) * LP_PITCH + l];
                    xw[i] = pack2(v, v);
                }
                const float* mrow = Ms + l * C_PAD + cbase;
#pragma unroll
                for (int u = 0; u < 7; ++u) {
                    unsigned long long m2 = *(const unsigned long long*)(mrow + (u << 1));
#pragma unroll
                    for (int i = 0; i < 4; ++i) accO[i][u] = fma2(xw[i], m2, accO[i][u]);
                }
            }
        }
    }

    // ---- write per-slice partials ----
    {
        const int cg = tid & 7;
#pragma unroll
        for (int i = 0; i < 4; ++i) {
            float* dst = g_part + ((size_t)sl * B_TOTAL + (b0 + bb + i)) * C_CLASSES;
#pragma unroll
            for (int u = 0; u < 7; ++u) {
                int c = cg * 14 + (u << 1);
                float lo, hi;
                unpack2(accO[i][u], lo, hi);
                if (c < C_CLASSES)     dst[c]     = lo;
                if (c + 1 < C_CLASSES) dst[c + 1] = hi;
            }
        }
    }
}

// ================= kernel 3: deterministic slice reduction =================
__global__ void reduce_kernel(float* __restrict__ out) {
    const int N = B_TOTAL * C_CLASSES;
    int i = blockIdx.x * blockDim.x + threadIdx.x;
    if (i < N)
        out[i] = g_part[i] + g_part[i + N] + g_part[i + 2 * N] + g_part[i + 3 * N];
}

// ================= launch =================
extern "C" void kernel_launch(void* const* d_in, const int* in_sizes, int n_in,
                              void* d_out, int out_size) {
    const float* x    = (const float*)d_in[0];   // [8192, 512]
    const float* W    = (const float*)d_in[1];   // [64, 63, 512]
    const float* bias = (const float*)d_in[2];   // [64, 63]
    const float* ll   = (const float*)d_in[3];   // [64, 64, 100]
    const float* tw   = (const float*)d_in[4];   // [64]
    float* out = (float*)d_out;                  // [8192, 100]

    cudaFuncSetAttribute(fused_tree_kernel,
                         cudaFuncAttributeMaxDynamicSharedMemorySize, SMEM_BYTES);

    softmax_mat_kernel<<<T_TREES * L_LEAVES, 32>>>(ll, tw);

    dim3 grid(B_TOTAL / TILE_B, NSLICES);        // 64 x 4 = 256 blocks
    fused_tree_kernel<<<grid, THREADS, SMEM_BYTES>>>(x, W, bias);

    const int N = B_TOTAL * C_CLASSES;
    reduce_kernel<<<(N + 255) / 256, 256>>>(out);
}

// round 2
// speedup vs baseline: 1.0012x; 1.0012x over previous
#include <cuda_runtime.h>
#include <cstdint>

// ---------------- problem constants ----------------
#define TD          6
#define T_TREES     64
#define N_NODES     63
#define L_LEAVES    64
#define C_CLASSES   100
#define C_PAD       112          // padded class dim (8 groups x 14)
#define B_TOTAL     8192
#define D_DIM       512

// ---------------- tiling ----------------
#define TILE_B      128
#define KC          64
#define NCHUNK      (D_DIM / KC)            // 8
#define NSLICES     4
#define TREES_PER_SLICE (T_TREES / NSLICES) // 16
#define THREADS     256

// ---------------- shared layout (floats) ----------------
// bufA union:  [Xs (64x128) | Ws (64x65)]  OR  [lp (128x65)]
#define XS_SIZE     (KC * 128)              // 8192
#define WS_OFF      XS_SIZE
#define WS_SIZE     (64 * 65)               // 4160
#define LP_PITCH    65
#define DEC_OFF     (XS_SIZE + WS_SIZE)     // 12352  (>= 128*65 lp)
#define DEC_PITCH   65
#define MS_OFF      (DEC_OFF + 128 * DEC_PITCH) // 20672
#define SMEM_FLOATS (MS_OFF + L_LEAVES * C_PAD) // 27840
#define SMEM_BYTES  (SMEM_FLOATS * 4)           // 111360

// ---------------- device scratch (no allocation allowed) ----------------
__device__ float g_M[T_TREES * L_LEAVES * C_PAD];            // softmax(leaf_logits)*tw, zero padded
__device__ float g_part[NSLICES * B_TOTAL * C_CLASSES];      // per-slice partial outputs

// ---------------- f32x2 helpers (Blackwell packed fp32) ----------------
__device__ __forceinline__ unsigned long long pack2(float lo, float hi) {
    unsigned long long r;
    asm("mov.b64 %0, {%1, %2};" : "=l"(r) : "f"(lo), "f"(hi));
    return r;
}
__device__ __forceinline__ void unpack2(unsigned long long v, float& lo, float& hi) {
    asm("mov.b64 {%0, %1}, %2;" : "=f"(lo), "=f"(hi) : "l"(v));
}
__device__ __forceinline__ unsigned long long fma2(unsigned long long a,
                                                   unsigned long long b,
                                                   unsigned long long c) {
    unsigned long long d;
    asm("fma.rn.f32x2 %0, %1, %2, %3;" : "=l"(d) : "l"(a), "l"(b), "l"(c));
    return d;
}

// ================= kernel 1: M[t,l,c] = softmax(leaf_logits[t,l,:])[c] * tw[t] =================
// one warp per (t,l) row
__global__ void softmax_mat_kernel(const float* __restrict__ ll, const float* __restrict__ tw) {
    const int row  = blockIdx.x;          // t*64 + l
    const int lane = threadIdx.x;
    const float* src = ll + (size_t)row * C_CLASSES;

    float v[4];
#pragma unroll
    for (int q = 0; q < 4; ++q) {
        int c = lane + 32 * q;
        v[q] = (c < C_CLASSES) ? src[c] : -1e30f;
    }
    float mx = fmaxf(fmaxf(v[0], v[1]), fmaxf(v[2], v[3]));
#pragma unroll
    for (int o = 16; o; o >>= 1) mx = fmaxf(mx, __shfl_xor_sync(0xffffffffu, mx, o));

    float e[4];
    float s = 0.f;
#pragma unroll
    for (int q = 0; q < 4; ++q) {
        int c = lane + 32 * q;
        e[q] = (c < C_CLASSES) ? __expf(v[q] - mx) : 0.f;
        s += e[q];
    }
#pragma unroll
    for (int o = 16; o; o >>= 1) s += __shfl_xor_sync(0xffffffffu, s, o);

    const float scale = tw[row >> 6] / s;
    float* dst = g_M + (size_t)row * C_PAD;
#pragma unroll
    for (int q = 0; q < 4; ++q) {
        int c = lane + 32 * q;
        if (c < C_PAD) dst[c] = (c < C_CLASSES) ? e[q] * scale : 0.f;
    }
}

// ================= kernel 2: fused trees =================
// grid: (B/128, 4 slices).  256 threads, occupancy 2 -> 256 blocks resident in one wave.
__global__ void __launch_bounds__(THREADS, 2)
fused_tree_kernel(const float* __restrict__ x,
                  const float* __restrict__ W,
                  const float* __restrict__ bias) {
    extern __shared__ float sm[];
    float* Xs  = sm;                 // [k][col] col = b ^ (k&28), pitch 128
    float* Ws  = sm + WS_OFF;        // [n][k]   pitch 65 (row 63 zeroed)
    float* lp  = sm;                 // [b][l]   pitch 65 (union with Xs/Ws)
    float* dec = sm + DEC_OFF;       // [b][n]   pitch 65
    float* Ms  = sm + MS_OFF;        // [l][c]   pitch 112

    const int tid = threadIdx.x;
    const int ng  = tid & 7;         // n-group (GEMM1) == c-group (GEMM2)
    const int bq  = tid >> 3;        // 0..31
    const int bb  = bq << 2;         // base b within tile (4 rows per thread)
    const int b0  = blockIdx.x * TILE_B;
    const int sl  = blockIdx.y;

    unsigned long long accO[4][7];   // output acc: 4 b-rows x 7 c-pairs (14 classes)
#pragma unroll
    for (int i = 0; i < 4; ++i)
#pragma unroll
        for (int u = 0; u < 7; ++u) accO[i][u] = 0ULL;

    for (int tt = 0; tt < TREES_PER_SLICE; ++tt) {
        const int t = sl * TREES_PER_SLICE + tt;

        __syncthreads();  // previous tree's GEMM2 (reads lp, Ms) fully done

        // ---- stage Ms for this tree: 64*112 floats = 1792 float4 ----
        {
            const float4* src = (const float4*)(g_M + (size_t)t * (L_LEAVES * C_PAD));
            float4* dst = (float4*)Ms;
#pragma unroll
            for (int it = 0; it < 7; ++it) dst[it * 256 + tid] = src[it * 256 + tid];
        }

        // ---- GEMM1: logits[128 x 64] = Xtile @ Wt^T ----
        unsigned long long acc0[8], acc1[8];  // (bb,bb+1) and (bb+2,bb+3) pairs x 8 nodes
#pragma unroll
        for (int j = 0; j < 8; ++j) { acc0[j] = 0ULL; acc1[j] = 0ULL; }

        for (int ch = 0; ch < NCHUNK; ++ch) {
            const int k0 = ch * KC;
            __syncthreads();  // previous chunk consumed before restaging

            // stage Xs: 128 rows x 64 k = 2048 float4, swizzled k-major
#pragma unroll
            for (int it = 0; it < 8; ++it) {
                int e4 = it * 256 + tid;
                int k4 = e4 & 15, b = e4 >> 4;
                float4 v = *(const float4*)(x + (size_t)(b0 + b) * D_DIM + k0 + (k4 << 2));
                int kk  = k4 << 2;
                int col = b ^ ((k4 & 7) << 2);   // == b ^ (k & 28)
                Xs[(kk + 0) * 128 + col] = v.x;
                Xs[(kk + 1) * 128 + col] = v.y;
                Xs[(kk + 2) * 128 + col] = v.z;
                Xs[(kk + 3) * 128 + col] = v.w;
            }
            // stage Ws: 64 n x 64 k = 1024 float4, n-major pitch 65 (row 63 zero)
#pragma unroll
            for (int it = 0; it < 4; ++it) {
                int e4 = it * 256 + tid;
                int k4 = e4 & 15, n = e4 >> 4;
                float4 v = make_float4(0.f, 0.f, 0.f, 0.f);
                if (n < N_NODES)
                    v = *(const float4*)(W + ((size_t)t * N_NODES + n) * D_DIM + k0 + (k4 << 2));
                float* wp = Ws + n * 65 + (k4 << 2);
                wp[0] = v.x; wp[1] = v.y; wp[2] = v.z; wp[3] = v.w;
            }
            __syncthreads();

            // inner product: per k, 2 LDS.64 (x pairs) + 8 LDS.32 (w) + 16 FFMA2
#pragma unroll 4
            for (int k = 0; k < KC; ++k) {
                const int colb = bb ^ (k & 28);
                const float* xk = Xs + k * 128;
                unsigned long long x20 = *(const unsigned long long*)(xk + colb);
                unsigned long long x21 = *(const unsigned long long*)(xk + (colb ^ 2));
                const float* wk = Ws + k;
#pragma unroll
                for (int j = 0; j < 8; ++j) {
                    float w = wk[(ng + (j << 3)) * 65];
                    unsigned long long w2 = pack2(w, w);
                    acc0[j] = fma2(x20, w2, acc0[j]);
                    acc1[j] = fma2(x21, w2, acc1[j]);
                }
            }
        }

        // ---- bias + sigmoid -> dec ----
        {
            const float* bt = bias + t * N_NODES;
#pragma unroll
            for (int j = 0; j < 8; ++j) {
                int n = ng + (j << 3);
                float bz = (n < N_NODES) ? bt[n] : 0.f;
                float a, b2, c, d;
                unpack2(acc0[j], a, b2);
                unpack2(acc1[j], c, d);
                dec[(bb + 0) * DEC_PITCH + n] = 1.f / (1.f + __expf(-(a  + bz)));
                dec[(bb + 1) * DEC_PITCH + n] = 1.f / (1.f + __expf(-(b2 + bz)));
                dec[(bb + 2) * DEC_PITCH + n] = 1.f / (1.f + __expf(-(c  + bz)));
                dec[(bb + 3) * DEC_PITCH + n] = 1.f / (1.f + __expf(-(d  + bz)));
            }
        }
        __syncthreads();

        // ---- leaf probabilities: lp[b][l] = prod over depth ----
        {
            int b  = tid >> 1;
            int l0 = (tid & 1) << 5;
            const float* db = dec + b * DEC_PITCH;
            float* lpb = lp + b * LP_PITCH;
#pragma unroll
            for (int li = 0; li < 32; ++li) {
                int l = l0 + li;
                float p = 1.f;
#pragma unroll
                for (int d = 0; d < TD; ++d) {
                    int node = (1 << d) - 1 + (l >> (TD - d));
                    float v = db[node];
                    p *= ((l >> (TD - 1 - d)) & 1) ? v : (1.f - v);
                }
                lpb[l] = p;
            }
        }
        __syncthreads();

        // ---- GEMM2: accO += lp[128 x 64] @ Ms[64 x 112] ----
        {
            const int cbase = ng * 14;
#pragma unroll 4
            for (int l = 0; l < L_LEAVES; ++l) {
                unsigned long long xw[4];
#pragma unroll
                for (int i = 0; i < 4; ++i) {
                    float v = lp[(bb + i) * LP_PITCH + l];
                    xw[i] = pack2(v, v);
                }
                const float* mrow = Ms + l * C_PAD + cbase;
#pragma unroll
                for (int u = 0; u < 7; ++u) {
                    unsigned long long m2 = *(const unsigned long long*)(mrow + (u << 1));
#pragma unroll
                    for (int i = 0; i < 4; ++i) accO[i][u] = fma2(xw[i], m2, accO[i][u]);
                }
            }
        }
    }

    // ---- write per-slice partials ----
    {
        const int cg = tid & 7;
#pragma unroll
        for (int i = 0; i < 4; ++i) {
            float* dst = g_part + ((size_t)sl * B_TOTAL + (b0 + bb + i)) * C_CLASSES;
#pragma unroll
            for (int u = 0; u < 7; ++u) {
                int c = cg * 14 + (u << 1);
                float lo, hi;
                unpack2(accO[i][u], lo, hi);
                if (c < C_CLASSES)     dst[c]     = lo;
                if (c + 1 < C_CLASSES) dst[c + 1] = hi;
            }
        }
    }
}

// ================= kernel 3: deterministic slice reduction =================
__global__ void reduce_kernel(float* __restrict__ out) {
    const int N = B_TOTAL * C_CLASSES;
    int i = blockIdx.x * blockDim.x + threadIdx.x;
    if (i < N)
        out[i] = g_part[i] + g_part[i + N] + g_part[i + 2 * N] + g_part[i + 3 * N];
}

// ================= launch =================
extern "C" void kernel_launch(void* const* d_in, const int* in_sizes, int n_in,
                              void* d_out, int out_size) {
    const float* x    = (const float*)d_in[0];   // [8192, 512]
    const float* W    = (const float*)d_in[1];   // [64, 63, 512]
    const float* bias = (const float*)d_in[2];   // [64, 63]
    const float* ll   = (const float*)d_in[3];   // [64, 64, 100]
    const float* tw   = (const float*)d_in[4];   // [64]
    float* out = (float*)d_out;                  // [8192, 100]

    cudaFuncSetAttribute(fused_tree_kernel,
                         cudaFuncAttributeMaxDynamicSharedMemorySize, SMEM_BYTES);

    softmax_mat_kernel<<<T_TREES * L_LEAVES, 32>>>(ll, tw);

    dim3 grid(B_TOTAL / TILE_B, NSLICES);        // 64 x 4 = 256 blocks
    fused_tree_kernel<<<grid, THREADS, SMEM_BYTES>>>(x, W, bias);

    const int N = B_TOTAL * C_CLASSES;
    reduce_kernel<<<(N + 255) / 256, 256>>>(out);
}

// round 4
// speedup vs baseline: 2.8848x; 2.8814x over previous
#include <cuda_runtime.h>
#include <cuda_bf16.h>
#include <cstdint>

#define N_NODES 63
#define C_CLASSES 100
#define B_TOT 8192
#define D_DIM 512
#define NTN 4096

// ---------------- device scratch ----------------
__device__ __nv_bfloat16 g_xh[B_TOT * D_DIM], g_xl[B_TOT * D_DIM];
__device__ __nv_bfloat16 g_wh[NTN * D_DIM], g_wl[NTN * D_DIM];
__device__ __nv_bfloat16 g_m[128 * NTN];                    // rows >=100 stay zero
__device__ __nv_bfloat16 g_lp[(size_t)B_TOT * NTN];

// ---------------- helpers ----------------
__device__ __forceinline__ uint32_t s2u(const void* p) {
    uint32_t a;
    asm("{ .reg .u64 t; cvta.to.shared.u64 t, %1; cvt.u32.u64 %0, t; }" : "=r"(a) : "l"(p));
    return a;
}
#define CP_COMMIT() asm volatile("cp.async.commit_group;" ::: "memory")
#define CP_WAIT(n)  asm volatile("cp.async.wait_group %0;" :: "n"(n) : "memory")
__device__ __forceinline__ void cp16(uint32_t dst, const void* src) {
    asm volatile("cp.async.cg.shared.global [%0], [%1], 16;" :: "r"(dst), "l"(src) : "memory");
}
// stage nRows x 128B (64 bf16) with XOR-8 swizzle on 16B units; 256 threads
__device__ __forceinline__ void stage_tile(uint32_t dstBase, const char* src, size_t rowB, int nRows) {
    const int units = nRows * 8;
    for (int u = threadIdx.x; u < units; u += 256) {
        int r = u >> 3, cu = u & 7;
        cp16(dstBase + (uint32_t)(((r << 3) + (cu ^ (r & 7))) << 4), src + (size_t)r * rowB + (cu << 4));
    }
}

#define LDSM4(a, addr) asm volatile( \
    "ldmatrix.sync.aligned.m8n8.x4.shared.b16 {%0,%1,%2,%3}, [%4];" \
    : "=r"((a)[0]), "=r"((a)[1]), "=r"((a)[2]), "=r"((a)[3]) : "r"(addr))
#define LDSM2(b, addr) asm volatile( \
    "ldmatrix.sync.aligned.m8n8.x2.shared.b16 {%0,%1}, [%2];" \
    : "=r"((b)[0]), "=r"((b)[1]) : "r"(addr))
#define MMA(c, a, b) asm volatile( \
    "mma.sync.aligned.m16n8k16.row.col.f32.bf16.bf16.f32 " \
    "{%0,%1,%2,%3},{%4,%5,%6,%7},{%8,%9},{%0,%1,%2,%3};" \
    : "+f"((c)[0]), "+f"((c)[1]), "+f"((c)[2]), "+f"((c)[3]) \
    : "r"((a)[0]), "r"((a)[1]), "r"((a)[2]), "r"((a)[3]), "r"((b)[0]), "r"((b)[1]))

// ============ prep ============
__global__ void prep_x(const float* __restrict__ x) {
    int i = blockIdx.x * 256 + threadIdx.x;
    float v = x[i];
    __nv_bfloat16 h = __float2bfloat16(v);
    g_xh[i] = h;
    g_xl[i] = __float2bfloat16(v - __bfloat162float(h));
}
__global__ void prep_w(const float* __restrict__ W) {
    int i = blockIdx.x * 256 + threadIdx.x;
    int row = i >> 9, k = i & 511, t = row >> 6, n = row & 63;
    float v = (n < N_NODES) ? W[((size_t)t * N_NODES + n) * D_DIM + k] : 0.f;
    __nv_bfloat16 h = __float2bfloat16(v);
    g_wh[i] = h;
    g_wl[i] = __float2bfloat16(v - __bfloat162float(h));
}
__global__ void prep_m(const float* __restrict__ ll, const float* __restrict__ tw) {
    int row = blockIdx.x * 8 + (threadIdx.x >> 5);   // t*64 + l
    int lane = threadIdx.x & 31;
    const float* src = ll + (size_t)row * C_CLASSES;
    float v[4];
#pragma unroll
    for (int q = 0; q < 4; ++q) { int c = lane + 32 * q; v[q] = (c < C_CLASSES) ? src[c] : -1e30f; }
    float mx = fmaxf(fmaxf(v[0], v[1]), fmaxf(v[2], v[3]));
#pragma unroll
    for (int o = 16; o; o >>= 1) mx = fmaxf(mx, __shfl_xor_sync(~0u, mx, o));
    float e[4], s = 0.f;
#pragma unroll
    for (int q = 0; q < 4; ++q) { int c = lane + 32 * q; e[q] = (c < C_CLASSES) ? __expf(v[q] - mx) : 0.f; s += e[q]; }
#pragma unroll
    for (int o = 16; o; o >>= 1) s += __shfl_xor_sync(~0u, s, o);
    float scale = tw[row >> 6] / s;
#pragma unroll
    for (int q = 0; q < 4; ++q) {
        int c = lane + 32 * q;
        if (c < C_CLASSES) g_m[(size_t)c * NTN + row] = __float2bfloat16(e[q] * scale);
    }
}

// ============ GEMM1 + sigmoid + leaf product fused ============
// grid (64, 32): 128 batch rows x 2 trees per CTA. 256 threads = 8 warps (2M x 4N).
#define G1_SOFF 1024
#define G1_BUF  32768                       // A 16KB + B 16KB per stage
#define G1_SMEM (G1_SOFF + 128 * 129 * 4)   // dec tile dominates: 67072

__global__ void __launch_bounds__(256) gemm1_kernel(const float* __restrict__ bias) {
    extern __shared__ char smem[];
    const uint32_t sb = s2u(smem);
    const int tid = threadIdx.x, wid = tid >> 5, lane = tid & 31;
    const int b0 = blockIdx.x * 128, ntb = blockIdx.y;

    if (tid < 126) {
        int tt = tid / 63, n = tid % 63;
        ((float*)(smem + 128))[tt * 64 + n] = bias[(ntb * 2 + tt) * N_NODES + n];
    }

    const char* xh = (const char*)g_xh + (size_t)b0 * 1024;
    const char* xl = (const char*)g_xl + (size_t)b0 * 1024;
    const char* wh = (const char*)g_wh + (size_t)(ntb * 128) * 1024;
    const char* wl = (const char*)g_wl + (size_t)(ntb * 128) * 1024;
    const char* Asrc[3] = {xh, xl, xh};
    const char* Bsrc[3] = {wh, wh, wl};

#define G1_SEG(seg) do { int _p = (seg) >> 3, _kc = (seg) & 7; \
    uint32_t _b = sb + G1_SOFF + ((seg) & 1) * G1_BUF; \
    stage_tile(_b, Asrc[_p] + _kc * 128, 1024, 128); \
    stage_tile(_b + 16384, Bsrc[_p] + _kc * 128, 1024, 128); \
    CP_COMMIT(); } while (0)

    // per-warp geometry
    const int wm = wid >> 2, wn = wid & 3;
    const int m0w = wm * 64, n0w = wn * 32;
    const uint32_t sx = lane & 7;
    const uint32_t aKh = (lane >> 4) & 1, bKh = (lane >> 3) & 1;
    uint32_t rA[4], rB[4];
#pragma unroll
    for (int mt = 0; mt < 4; ++mt) rA[mt] = (uint32_t)(m0w + mt * 16 + (lane & 15)) * 128;
#pragma unroll
    for (int nt = 0; nt < 4; ++nt) rB[nt] = (uint32_t)(n0w + nt * 8 + (lane & 7)) * 128;

    float acc[4][4][4];
#pragma unroll
    for (int mt = 0; mt < 4; ++mt)
#pragma unroll
        for (int nt = 0; nt < 4; ++nt)
#pragma unroll
            for (int q = 0; q < 4; ++q) acc[mt][nt][q] = 0.f;

    G1_SEG(0); G1_SEG(1);
#pragma unroll 1
    for (int seg = 0; seg < 24; ++seg) {
        if (seg < 23) { CP_WAIT(1); } else { CP_WAIT(0); }
        __syncthreads();
        uint32_t Ab = sb + G1_SOFF + (seg & 1) * G1_BUF;
        uint32_t Bb = Ab + 16384;
#pragma unroll
        for (int ks = 0; ks < 4; ++ks) {
            uint32_t a[4][4], b[4][2];
#pragma unroll
            for (int mt = 0; mt < 4; ++mt)
                LDSM4(a[mt], Ab + rA[mt] + ((((uint32_t)ks * 2 + aKh) ^ sx) << 4));
#pragma unroll
            for (int nt = 0; nt < 4; ++nt)
                LDSM2(b[nt], Bb + rB[nt] + ((((uint32_t)ks * 2 + bKh) ^ sx) << 4));
#pragma unroll
            for (int mt = 0; mt < 4; ++mt)
#pragma unroll
                for (int nt = 0; nt < 4; ++nt)
                    MMA(acc[mt][nt], a[mt], b[nt]);
        }
        __syncthreads();
        if (seg + 2 < 24) G1_SEG(seg + 2);
    }

    // acc -> dec smem (pitch 129 floats)
    float* dec = (float*)(smem + G1_SOFF);
    {
        const int r = lane >> 2, c2 = (lane & 3) * 2;
#pragma unroll
        for (int mt = 0; mt < 4; ++mt)
#pragma unroll
            for (int nt = 0; nt < 4; ++nt) {
                int row = m0w + mt * 16 + r, col = n0w + nt * 8 + c2;
                dec[row * 129 + col]           = acc[mt][nt][0];
                dec[row * 129 + col + 1]       = acc[mt][nt][1];
                dec[(row + 8) * 129 + col]     = acc[mt][nt][2];
                dec[(row + 8) * 129 + col + 1] = acc[mt][nt][3];
            }
    }
    __syncthreads();

    // per-thread: one (row, tree): sigmoid + leaf product + bf16 store
    {
        const int row = tid & 127, tt = tid >> 7;
        const float* bs = ((const float*)(smem + 128)) + tt * 64;
        const float* dr = dec + row * 129 + tt * 64;
        float dc[63];
#pragma unroll
        for (int n = 0; n < 63; ++n)
            dc[n] = __fdividef(1.f, 1.f + __expf(-(dr[n] + bs[n])));
        float p[64];
        p[0] = 1.f;
#pragma unroll
        for (int d = 0; d < 6; ++d)
#pragma unroll
            for (int i = (1 << d) - 1; i >= 0; --i) {
                float v = dc[(1 << d) - 1 + i], pi = p[i];
                p[2 * i + 1] = pi * v;
                p[2 * i]     = pi * (1.f - v);
            }
        __nv_bfloat16 ob[64];
#pragma unroll
        for (int l = 0; l < 64; ++l) ob[l] = __float2bfloat16(p[l]);
        uint4* dst = (uint4*)(g_lp + (size_t)(b0 + row) * NTN + ntb * 128 + tt * 64);
        const uint4* srcv = (const uint4*)ob;
#pragma unroll
        for (int q = 0; q < 8; ++q) dst[q] = srcv[q];
    }
}

// ============ GEMM2: out[8192,100] = lp @ M^T ============
// grid 128: 64 batch rows x 128 classes (>=100 zero). 8 warps (2M x 4N), warp 32x32.
#define G2_SOFF 1024
#define G2_BUF  24576                       // A 8KB + B 16KB
#define G2_SMEM (G2_SOFF + 2 * G2_BUF)      // 50176

__global__ void __launch_bounds__(256) gemm2_kernel(float* __restrict__ out) {
    extern __shared__ char smem[];
    const uint32_t sb = s2u(smem);
    const int tid = threadIdx.x, wid = tid >> 5, lane = tid & 31;
    const int b0 = blockIdx.x * 64;

    const char* Ag = (const char*)g_lp + (size_t)b0 * 8192;
    const char* Bg = (const char*)g_m;

#define G2_SEG(seg) do { uint32_t _b = sb + G2_SOFF + ((seg) & 1) * G2_BUF; \
    stage_tile(_b, Ag + (size_t)(seg) * 128, 8192, 64); \
    stage_tile(_b + 8192, Bg + (size_t)(seg) * 128, 8192, 128); \
    CP_COMMIT(); } while (0)

    const int wm = wid >> 2, wn = wid & 3;
    const int m0w = wm * 32, n0w = wn * 32;
    const uint32_t sx = lane & 7;
    const uint32_t aKh = (lane >> 4) & 1, bKh = (lane >> 3) & 1;
    uint32_t rA[2], rB[4];
#pragma unroll
    for (int mt = 0; mt < 2; ++mt) rA[mt] = (uint32_t)(m0w + mt * 16 + (lane & 15)) * 128;
#pragma unroll
    for (int nt = 0; nt < 4; ++nt) rB[nt] = (uint32_t)(n0w + nt * 8 + (lane & 7)) * 128;

    float acc[2][4][4];
#pragma unroll
    for (int mt = 0; mt < 2; ++mt)
#pragma unroll
        for (int nt = 0; nt < 4; ++nt)
#pragma unroll
            for (int q = 0; q < 4; ++q) acc[mt][nt][q] = 0.f;

    G2_SEG(0); G2_SEG(1);
#pragma unroll 1
    for (int seg = 0; seg < 64; ++seg) {
        if (seg < 63) { CP_WAIT(1); } else { CP_WAIT(0); }
        __syncthreads();
        uint32_t Ab = sb + G2_SOFF + (seg & 1) * G2_BUF;
        uint32_t Bb = Ab + 8192;
#pragma unroll
        for (int ks = 0; ks < 4; ++ks) {
            uint32_t a[2][4], b[4][2];
#pragma unroll
            for (int mt = 0; mt < 2; ++mt)
                LDSM4(a[mt], Ab + rA[mt] + ((((uint32_t)ks * 2 + aKh) ^ sx) << 4));
#pragma unroll
            for (int nt = 0; nt < 4; ++nt)
                LDSM2(b[nt], Bb + rB[nt] + ((((uint32_t)ks * 2 + bKh) ^ sx) << 4));
#pragma unroll
            for (int mt = 0; mt < 2; ++mt)
#pragma unroll
                for (int nt = 0; nt < 4; ++nt)
                    MMA(acc[mt][nt], a[mt], b[nt]);
        }
        __syncthreads();
        if (seg + 2 < 64) G2_SEG(seg + 2);
    }

    // write fp32 output (guard class < 100)
    {
        const int r = lane >> 2, c2 = (lane & 3) * 2;
#pragma unroll
        for (int mt = 0; mt < 2; ++mt)
#pragma unroll
            for (int nt = 0; nt < 4; ++nt) {
                int row = b0 + m0w + mt * 16 + r;
                int col = n0w + nt * 8 + c2;
                if (col < C_CLASSES) {
                    out[(size_t)row * C_CLASSES + col]       = acc[mt][nt][0];
                    out[(size_t)(row + 8) * C_CLASSES + col] = acc[mt][nt][2];
                }
                if (col + 1 < C_CLASSES) {
                    out[(size_t)row * C_CLASSES + col + 1]       = acc[mt][nt][1];
                    out[(size_t)(row + 8) * C_CLASSES + col + 1] = acc[mt][nt][3];
                }
            }
    }
}

// ============ launch ============
extern "C" void kernel_launch(void* const* d_in, const int* in_sizes, int n_in,
                              void* d_out, int out_size) {
    const float* x    = (const float*)d_in[0];
    const float* W    = (const float*)d_in[1];
    const float* bias = (const float*)d_in[2];
    const float* ll   = (const float*)d_in[3];
    const float* tw   = (const float*)d_in[4];
    float* out = (float*)d_out;

    cudaFuncSetAttribute(gemm1_kernel, cudaFuncAttributeMaxDynamicSharedMemorySize, G1_SMEM);
    cudaFuncSetAttribute(gemm2_kernel, cudaFuncAttributeMaxDynamicSharedMemorySize, G2_SMEM);

    prep_x<<<B_TOT * D_DIM / 256, 256>>>(x);
    prep_w<<<NTN * D_DIM / 256, 256>>>(W);
    prep_m<<<512, 256>>>(ll, tw);
    gemm1_kernel<<<dim3(64, 32), 256, G1_SMEM>>>(bias);
    gemm2_kernel<<<128, 256, G2_SMEM>>>(out);
}